// round 15
// baseline (speedup 1.0000x reference)
#include <cuda_runtime.h>
#include <math.h>
#include <stdint.h>

#define NB    34
#define CTOT  128
#define TLEN  2000
#define BATCH 8
#define ROW2  481
#define P     964
#define CCH   32
#define TT    16
#define NTH   512
#define TCH   8

__constant__ int c_W[NB] = {
  10, 8,8,8,8,8,8,8,8,8,8,8,8,8,8,8,8,8,8,8,
  20,20,20,20,20,20, 80,80,80,80,80,80,80, 120};
__constant__ int c_F0[NB] = {
  0, 10,18,26,34,42,50,58,66,74,82,90,98,106,114,122,130,138,146,154,
  162,182,202,222,242,262, 282,362,442,522,602,682,762, 842};
__constant__ int c_WO[NB] = {
  0, 12,20,28,36,44,52,60,68,76,84,92,100,108,116,124,132,140,148,156,
  164,184,204,224,244,264, 284,364,444,524,604,684,764, 844};
__constant__ int c_G[NB] = {
  0, 1,1,1,1,1,1,1,1,1,1,1,1,1,1,1,1,1,1,1,
  2,2,2,2,2,2, 3,3,3,3,3,3,3, 4};
__constant__ int c_K[NB] = {
  0, 0,1,2,3,4,5,6,7,8,9,10,11,12,13,14,15,16,17,18,
  0,1,2,3,4,5, 0,1,2,3,4,5,6, 0};

__device__ float g_S   [NB * CTOT];
__device__ float g_fbe [NB * CTOT];
__device__ float g_rstd[BATCH * NB];
__device__ float2 g_part[BATCH * NB * TCH];
__device__ __align__(16) float g_fwe  [CTOT * P];           // nw*fw, batch-independent
__device__ __align__(16) float g_binit[BATCH * CTOT * NB];  // fbe - mu*rstd*S

struct GParams {
  const float* nw[5]; const float* nb[5];
  const float* fw[5]; const float* fb[5];
};

// ===== K0: batch-independent effective weights + S + fbe =====
__global__ void k0_prep(GParams p) {
  const int j = blockIdx.x;          // band
  const int c = threadIdx.x;         // channel 0..127
  const int g = c_G[j], k = c_K[j], w = c_W[j], wo = c_WO[j];
  const float* nw = p.nw[g] + k * w;
  const float* nb = p.nb[g] + k * w;
  const float* fw = p.fw[g] + (size_t)(k * CTOT + c) * w;
  float S = 0.f, nbd = 0.f;
  for (int fl = 0; fl < w; ++fl) {
    const float v = nw[fl] * fw[fl];
    g_fwe[c * P + wo + fl] = v;
    S += v;
    nbd = fmaf(nb[fl], fw[fl], nbd);
  }
  if (j == 0) {                      // zero the 2 pad slots of band 0
    g_fwe[c * P + 10] = 0.f;
    g_fwe[c * P + 11] = 0.f;
  }
  g_S  [j * CTOT + c] = S;
  g_fbe[j * CTOT + c] = p.fb[g][k * CTOT + c] + nbd;
}

// ===== K1: partial stats per (band, b, t-chunk) =====
__global__ void k1_stats(const float* __restrict__ x) {
  const int j = blockIdx.x, b = blockIdx.y, ch = blockIdx.z;
  const int tid = threadIdx.x;       // 128
  const int w = c_W[j], f0 = c_F0[j];
  const int t0 = ch * (TLEN / TCH);
  const float2* x2 = (const float2*)x;
  float s = 0.f, q = 0.f;
  const int wh = w >> 1;
  for (int t = tid; t < TLEN / TCH; t += 128) {
    const float2* r = x2 + (size_t)(b * TLEN + t0 + t) * ROW2 + (f0 >> 1);
#pragma unroll 4
    for (int h = 0; h < wh; ++h) {
      float2 v = r[h];
      s += v.x + v.y;
      q = fmaf(v.x, v.x, q);
      q = fmaf(v.y, v.y, q);
    }
  }
#pragma unroll
  for (int o = 16; o; o >>= 1) {
    s += __shfl_down_sync(0xffffffffu, s, o);
    q += __shfl_down_sync(0xffffffffu, q, o);
  }
  __shared__ float ss[4], qs[4];
  const int lane = tid & 31, wid = tid >> 5;
  if (lane == 0) { ss[wid] = s; qs[wid] = q; }
  __syncthreads();
  if (tid == 0) {
    g_part[(b * NB + j) * TCH + ch] =
      make_float2(ss[0]+ss[1]+ss[2]+ss[3], qs[0]+qs[1]+qs[2]+qs[3]);
  }
}

// ===== K2-lite: reduce stats -> rstd + binit (tiny) =====
__global__ void k2_lite(void) {
  const int b = blockIdx.x;          // 0..7
  const int c = threadIdx.x;         // 128
  __shared__ float s_mu[NB], s_rs[NB];
  if (c < NB) {
    const int j = c;
    float S = 0.f, Q = 0.f;
#pragma unroll
    for (int k = 0; k < TCH; ++k) {
      float2 v = g_part[(b * NB + j) * TCH + k];
      S += v.x; Q += v.y;
    }
    const float invN = 1.f / (float)(TLEN * c_W[j]);
    const float mu = S * invN;
    const float rs = rsqrtf(Q * invN - mu * mu + 1e-5f);
    s_mu[j] = mu; s_rs[j] = rs;
    g_rstd[b * NB + j] = rs;
  }
  __syncthreads();
#pragma unroll 2
  for (int j = 0; j < NB; ++j) {
    g_binit[(size_t)(b * CTOT + c) * NB + j] =
      g_fbe[j * CTOT + c] - s_mu[j] * s_rs[j] * g_S[j * CTOT + c];
  }
}

// ===== main: R11 champion compute; rstd folded at band end =====
#define SMF_W  (CCH * P)
#define SMF_X  (TT * P)
#define SMF_B  (CCH * NB)
#define SM_BYTES  ((SMF_W + SMF_X + SMF_B + 40) * 4)
#define STG_STRIDE 548     // 2192 B, 16B-aligned

// X(accIdx, band, paddedOffset, width). Range widths 236/252/240/236.
#define RANGE_A(X) \
  X(0,33,844,120) X(1,0,0,12) X(2,1,12,8) X(3,2,20,8) X(4,3,28,8) X(5,4,36,8) \
  X(6,5,44,8) X(7,6,52,8) X(8,7,60,8) X(9,8,68,8) X(10,23,224,20) X(11,24,244,20)
#define RANGE_B(X) \
  X(0,32,764,80) X(1,26,284,80) X(2,9,76,8) X(3,10,84,8) X(4,11,92,8) X(5,12,100,8) \
  X(6,13,108,8) X(7,14,116,8) X(8,15,124,8) X(9,16,132,8) X(10,17,140,8) X(11,25,264,20)
#define RANGE_C(X) X(0,27,364,80) X(1,28,444,80) X(2,29,524,80)
#define RANGE_D(X) \
  X(0,30,604,80) X(1,31,684,80) X(2,18,148,8) X(3,19,156,8) X(4,20,164,20) \
  X(5,21,184,20) X(6,22,204,20)

__device__ __forceinline__ void cpa16(uint32_t s, const void* g) {
  asm volatile("cp.async.cg.shared.global [%0], [%1], 16;\n" :: "r"(s), "l"(g));
}
__device__ __forceinline__ void cpa8(uint32_t s, const void* g) {
  asm volatile("cp.async.ca.shared.global [%0], [%1], 8;\n" :: "r"(s), "l"(g));
}
__device__ __forceinline__ void fma2(unsigned long long& a,
                                     unsigned long long xv,
                                     unsigned long long wv) {
  asm("fma.rn.f32x2 %0, %1, %2, %0;" : "+l"(a) : "l"(xv), "l"(wv));
}
__device__ __forceinline__ float hadd2(unsigned long long a) {
  float lo, hi;
  asm("mov.b64 {%0, %1}, %2;" : "=f"(lo), "=f"(hi) : "l"(a));
  return lo + hi;
}

// per band: f32x2 partials over even/odd f; fold bias + rstd scale at end
#define COMPB(I, J, WO, WL) { \
  unsigned long long a0 = 0ull, a1 = 0ull, a2 = 0ull, a3 = 0ull; \
  _Pragma("unroll") \
  for (int f = 0; f < (WL); f += 4) { \
    const ulonglong2 wv = *(const ulonglong2*)(wr  + (WO) + f); \
    const ulonglong2 v0 = *(const ulonglong2*)(xr0 + (WO) + f); \
    const ulonglong2 v1 = *(const ulonglong2*)(xr1 + (WO) + f); \
    const ulonglong2 v2 = *(const ulonglong2*)(xr2 + (WO) + f); \
    const ulonglong2 v3 = *(const ulonglong2*)(xr3 + (WO) + f); \
    fma2(a0, v0.x, wv.x); fma2(a0, v0.y, wv.y); \
    fma2(a1, v1.x, wv.x); fma2(a1, v1.y, wv.y); \
    fma2(a2, v2.x, wv.x); fma2(a2, v2.y, wv.y); \
    fma2(a3, v3.x, wv.x); fma2(a3, v3.y, wv.y); \
  } \
  { const float bi = s_binit[cc * NB + (J)]; \
    const float rs = s_rs[(J)]; \
    acc[I][0] = fmaf(rs, hadd2(a0), bi); \
    acc[I][1] = fmaf(rs, hadd2(a1), bi); \
    acc[I][2] = fmaf(rs, hadd2(a2), bi); \
    acc[I][3] = fmaf(rs, hadd2(a3), bi); } }

// thread's t rows: t(q) = th8 + 2q + tl
#define STAGEB(I, J, WO, WL) { \
  stg[cc * STG_STRIDE + (th8 + 0 + tl) * NB + (J)] = acc[I][0]; \
  stg[cc * STG_STRIDE + (th8 + 2 + tl) * NB + (J)] = acc[I][1]; \
  stg[cc * STG_STRIDE + (th8 + 4 + tl) * NB + (J)] = acc[I][2]; \
  stg[cc * STG_STRIDE + (th8 + 6 + tl) * NB + (J)] = acc[I][3]; }

__global__ void __launch_bounds__(NTH, 1)
main_kernel(const float* __restrict__ x, float* __restrict__ out) {
  extern __shared__ float sm[];
  float* s_w     = sm;
  float* s_x     = sm + SMF_W;
  float* s_binit = sm + SMF_W + SMF_X;
  float* s_rs    = s_binit + SMF_B;
  float* stg     = sm;                 // overlays s_w after compute

  const int tid  = threadIdx.x;
  const int lane = tid & 31;
  const int wid  = tid >> 5;           // warp 0..15
  const int rng  = wid >> 2;           // band range 0..3
  const int sub  = wid & 3;            // SMSP id: (c-half, t-half)
  const int chh  = sub & 1;
  const int th   = sub >> 1;
  const int cl   = lane & 15;
  const int tl   = lane >> 4;
  const int cc   = chh * 16 + cl;      // channel within block 0..31
  const int th8  = th * 8;
  const int c0 = blockIdx.x * CCH;
  const int t0 = blockIdx.y * TT;
  const int b  = blockIdx.z;

  const uint32_t sb = (uint32_t)__cvta_generic_to_shared(sm);

  // ---- cooperative async loads: weights (batch-indep, L2-hot) + x + binit ----
  {
    const float4* gw = (const float4*)(g_fwe + (size_t)c0 * P);
    for (int i = tid; i < CCH * (P / 4); i += NTH)
      cpa16(sb + (uint32_t)i * 16u, gw + i);
    const float2* gx = (const float2*)x + (size_t)(b * TLEN + t0) * ROW2;
    for (int i = tid; i < TT * ROW2; i += NTH) {
      const int r = i / ROW2, pp = i - r * ROW2;
      const int dst = r * (P / 2) + pp + (pp >= 5 ? 1 : 0);
      cpa8(sb + (uint32_t)(SMF_W * 4) + (uint32_t)dst * 8u, gx + i);
    }
    const float4* gb = (const float4*)(g_binit + (size_t)((b << 7) + c0) * NB);
    for (int i = tid; i < (CCH * NB) / 4; i += NTH)
      cpa16(sb + (uint32_t)((SMF_W + SMF_X) * 4) + (uint32_t)i * 16u, gb + i);
    asm volatile("cp.async.commit_group;\n" ::);
  }
  if (tid < NB) s_rs[tid] = g_rstd[b * NB + tid];   // direct LDG+STS
  asm volatile("cp.async.wait_group 0;\n" ::);
  if (tid < 2 * TT) s_x[(tid >> 1) * P + 10 + (tid & 1)] = 0.f;  // pad slots
  __syncthreads();

  const float* wr  = s_w + cc * P;
  const float* xr0 = s_x + (th8 + 0 + tl) * P;
  const float* xr1 = s_x + (th8 + 2 + tl) * P;
  const float* xr2 = s_x + (th8 + 4 + tl) * P;
  const float* xr3 = s_x + (th8 + 6 + tl) * P;

  float acc[12][4];

  if      (rng == 0) { RANGE_A(COMPB) }
  else if (rng == 1) { RANGE_B(COMPB) }
  else if (rng == 2) { RANGE_C(COMPB) }
  else               { RANGE_D(COMPB) }

  __syncthreads();     // all smem reads done before stage overlays s_w

  if      (rng == 0) { RANGE_A(STAGEB) }
  else if (rng == 1) { RANGE_B(STAGEB) }
  else if (rng == 2) { RANGE_C(STAGEB) }
  else               { RANGE_D(STAGEB) }
  __syncthreads();

  // coalesced float4 flush: per channel, 16 t-rows contiguous (544 floats)
  const size_t ob0 = ((size_t)((b << 7) + c0) * TLEN + t0) * NB;
#pragma unroll
  for (int k = 0; k < 9; ++k) {
    const int i = tid + (k << 9);
    if (i < 4352) {
      const int c = i / 136;
      const int q = i - c * 136;
      const float4 v = *(const float4*)(stg + c * STG_STRIDE + (q << 2));
      *(float4*)(out + ob0 + (size_t)c * (TLEN * NB) + (q << 2)) = v;
    }
  }
}

// ===== launch =====
extern "C" void kernel_launch(void* const* d_in, const int* in_sizes, int n_in,
                              void* d_out, int out_size) {
  (void)in_sizes; (void)n_in; (void)out_size;
  const float* x = (const float*)d_in[0];
  float* out = (float*)d_out;

  GParams p;
  for (int g = 0; g < 5; ++g) {
    p.nw[g] = (const float*)d_in[1 + 4 * g + 0];
    p.nb[g] = (const float*)d_in[1 + 4 * g + 1];
    p.fw[g] = (const float*)d_in[1 + 4 * g + 2];
    p.fb[g] = (const float*)d_in[1 + 4 * g + 3];
  }

  static bool attr_set = false;
  if (!attr_set) {
    cudaFuncSetAttribute(main_kernel, cudaFuncAttributeMaxDynamicSharedMemorySize, SM_BYTES);
    attr_set = true;
  }

  k0_prep<<<NB, CTOT>>>(p);
  k1_stats<<<dim3(NB, BATCH, TCH), 128>>>(x);
  k2_lite<<<BATCH, 128>>>();
  main_kernel<<<dim3(CTOT / CCH, TLEN / TT, BATCH), NTH, SM_BYTES>>>(x, out);
}

// round 16
// speedup vs baseline: 1.0676x; 1.0676x over previous
#include <cuda_runtime.h>
#include <math.h>
#include <stdint.h>

#define NB    34
#define CTOT  128
#define TLEN  2000
#define BATCH 8
#define ROW2  481
#define P     964
#define CCH   32
#define TT    16
#define NTH   512
#define TCH   8

__constant__ int c_W[NB] = {
  10, 8,8,8,8,8,8,8,8,8,8,8,8,8,8,8,8,8,8,8,
  20,20,20,20,20,20, 80,80,80,80,80,80,80, 120};
__constant__ int c_F0[NB] = {
  0, 10,18,26,34,42,50,58,66,74,82,90,98,106,114,122,130,138,146,154,
  162,182,202,222,242,262, 282,362,442,522,602,682,762, 842};
__constant__ int c_WO[NB] = {
  0, 12,20,28,36,44,52,60,68,76,84,92,100,108,116,124,132,140,148,156,
  164,184,204,224,244,264, 284,364,444,524,604,684,764, 844};
__constant__ int c_G[NB] = {
  0, 1,1,1,1,1,1,1,1,1,1,1,1,1,1,1,1,1,1,1,
  2,2,2,2,2,2, 3,3,3,3,3,3,3, 4};
__constant__ int c_K[NB] = {
  0, 0,1,2,3,4,5,6,7,8,9,10,11,12,13,14,15,16,17,18,
  0,1,2,3,4,5, 0,1,2,3,4,5,6, 0};

__device__ float g_S   [NB * CTOT];
__device__ float g_fbe [NB * CTOT];
__device__ float g_rstd[BATCH * NB];
__device__ float2 g_part[BATCH * NB * TCH];
__device__ __align__(16) float g_fwe  [CTOT * P];           // nw*fw, batch-independent
__device__ __align__(16) float g_binit[BATCH * CTOT * NB];  // fbe - mu*rstd*S

struct GParams {
  const float* nw[5]; const float* nb[5];
  const float* fw[5]; const float* fb[5];
};

// ===== K1: stats (z<TCH) + prep g_fwe/S/fbe (z==TCH, hidden in same launch) =====
__global__ void k1_fused(GParams p, const float* __restrict__ x) {
  const int j = blockIdx.x, b = blockIdx.y, ch = blockIdx.z;
  const int tid = threadIdx.x;       // 128
  if (ch == TCH) {
    if (b != 0) return;              // 34 prep blocks, overlapped with stats
    const int c = tid;
    const int g = c_G[j], k = c_K[j], w = c_W[j], wo = c_WO[j];
    const float* nw = p.nw[g] + k * w;
    const float* nb = p.nb[g] + k * w;
    const float* fw = p.fw[g] + (size_t)(k * CTOT + c) * w;
    float S = 0.f, nbd = 0.f;
    for (int fl = 0; fl < w; ++fl) {
      const float v = nw[fl] * fw[fl];
      g_fwe[c * P + wo + fl] = v;
      S += v;
      nbd = fmaf(nb[fl], fw[fl], nbd);
    }
    if (j == 0) {                    // zero the 2 pad slots of band 0
      g_fwe[c * P + 10] = 0.f;
      g_fwe[c * P + 11] = 0.f;
    }
    g_S  [j * CTOT + c] = S;
    g_fbe[j * CTOT + c] = p.fb[g][k * CTOT + c] + nbd;
    return;
  }
  // ---- partial stats over t-chunk ----
  const int w = c_W[j], f0 = c_F0[j];
  const int t0 = ch * (TLEN / TCH);
  const float2* x2 = (const float2*)x;
  float s = 0.f, q = 0.f;
  const int wh = w >> 1;
  for (int t = tid; t < TLEN / TCH; t += 128) {
    const float2* r = x2 + (size_t)(b * TLEN + t0 + t) * ROW2 + (f0 >> 1);
#pragma unroll 4
    for (int h = 0; h < wh; ++h) {
      float2 v = r[h];
      s += v.x + v.y;
      q = fmaf(v.x, v.x, q);
      q = fmaf(v.y, v.y, q);
    }
  }
#pragma unroll
  for (int o = 16; o; o >>= 1) {
    s += __shfl_down_sync(0xffffffffu, s, o);
    q += __shfl_down_sync(0xffffffffu, q, o);
  }
  __shared__ float ss[4], qs[4];
  const int lane = tid & 31, wid = tid >> 5;
  if (lane == 0) { ss[wid] = s; qs[wid] = q; }
  __syncthreads();
  if (tid == 0) {
    g_part[(b * NB + j) * TCH + ch] =
      make_float2(ss[0]+ss[1]+ss[2]+ss[3], qs[0]+qs[1]+qs[2]+qs[3]);
  }
}

// ===== K2-lite: reduce stats -> rstd + binit (tiny) =====
__global__ void k2_lite(void) {
  const int b = blockIdx.x;          // 0..7
  const int c = threadIdx.x;         // 128
  __shared__ float s_mu[NB], s_rs[NB];
  if (c < NB) {
    const int j = c;
    float S = 0.f, Q = 0.f;
#pragma unroll
    for (int k = 0; k < TCH; ++k) {
      float2 v = g_part[(b * NB + j) * TCH + k];
      S += v.x; Q += v.y;
    }
    const float invN = 1.f / (float)(TLEN * c_W[j]);
    const float mu = S * invN;
    const float rs = rsqrtf(Q * invN - mu * mu + 1e-5f);
    s_mu[j] = mu; s_rs[j] = rs;
    g_rstd[b * NB + j] = rs;
  }
  __syncthreads();
#pragma unroll 2
  for (int j = 0; j < NB; ++j) {
    g_binit[(size_t)(b * CTOT + c) * NB + j] =
      g_fbe[j * CTOT + c] - s_mu[j] * s_rs[j] * g_S[j * CTOT + c];
  }
}

// ===== main: R15-measured compute (278.9 us), batch-indep weights + rstd fold =====
#define SMF_W  (CCH * P)
#define SMF_X  (TT * P)
#define SMF_B  (CCH * NB)
#define SM_BYTES  ((SMF_W + SMF_X + SMF_B + 40) * 4)
#define STG_STRIDE 548     // 2192 B, 16B-aligned

// X(accIdx, band, paddedOffset, width). Range widths 236/252/240/236.
#define RANGE_A(X) \
  X(0,33,844,120) X(1,0,0,12) X(2,1,12,8) X(3,2,20,8) X(4,3,28,8) X(5,4,36,8) \
  X(6,5,44,8) X(7,6,52,8) X(8,7,60,8) X(9,8,68,8) X(10,23,224,20) X(11,24,244,20)
#define RANGE_B(X) \
  X(0,32,764,80) X(1,26,284,80) X(2,9,76,8) X(3,10,84,8) X(4,11,92,8) X(5,12,100,8) \
  X(6,13,108,8) X(7,14,116,8) X(8,15,124,8) X(9,16,132,8) X(10,17,140,8) X(11,25,264,20)
#define RANGE_C(X) X(0,27,364,80) X(1,28,444,80) X(2,29,524,80)
#define RANGE_D(X) \
  X(0,30,604,80) X(1,31,684,80) X(2,18,148,8) X(3,19,156,8) X(4,20,164,20) \
  X(5,21,184,20) X(6,22,204,20)

__device__ __forceinline__ void cpa16(uint32_t s, const void* g) {
  asm volatile("cp.async.cg.shared.global [%0], [%1], 16;\n" :: "r"(s), "l"(g));
}
__device__ __forceinline__ void cpa8(uint32_t s, const void* g) {
  asm volatile("cp.async.ca.shared.global [%0], [%1], 8;\n" :: "r"(s), "l"(g));
}
__device__ __forceinline__ void fma2(unsigned long long& a,
                                     unsigned long long xv,
                                     unsigned long long wv) {
  asm("fma.rn.f32x2 %0, %1, %2, %0;" : "+l"(a) : "l"(xv), "l"(wv));
}
__device__ __forceinline__ float hadd2(unsigned long long a) {
  float lo, hi;
  asm("mov.b64 {%0, %1}, %2;" : "=f"(lo), "=f"(hi) : "l"(a));
  return lo + hi;
}

// per band: f32x2 partials over even/odd f; fold bias + rstd scale at end
#define COMPB(I, J, WO, WL) { \
  unsigned long long a0 = 0ull, a1 = 0ull, a2 = 0ull, a3 = 0ull; \
  _Pragma("unroll") \
  for (int f = 0; f < (WL); f += 4) { \
    const ulonglong2 wv = *(const ulonglong2*)(wr  + (WO) + f); \
    const ulonglong2 v0 = *(const ulonglong2*)(xr0 + (WO) + f); \
    const ulonglong2 v1 = *(const ulonglong2*)(xr1 + (WO) + f); \
    const ulonglong2 v2 = *(const ulonglong2*)(xr2 + (WO) + f); \
    const ulonglong2 v3 = *(const ulonglong2*)(xr3 + (WO) + f); \
    fma2(a0, v0.x, wv.x); fma2(a0, v0.y, wv.y); \
    fma2(a1, v1.x, wv.x); fma2(a1, v1.y, wv.y); \
    fma2(a2, v2.x, wv.x); fma2(a2, v2.y, wv.y); \
    fma2(a3, v3.x, wv.x); fma2(a3, v3.y, wv.y); \
  } \
  { const float bi = s_binit[cc * NB + (J)]; \
    const float rs = s_rs[(J)]; \
    acc[I][0] = fmaf(rs, hadd2(a0), bi); \
    acc[I][1] = fmaf(rs, hadd2(a1), bi); \
    acc[I][2] = fmaf(rs, hadd2(a2), bi); \
    acc[I][3] = fmaf(rs, hadd2(a3), bi); } }

// thread's t rows: t(q) = th8 + 2q + tl
#define STAGEB(I, J, WO, WL) { \
  stg[cc * STG_STRIDE + (th8 + 0 + tl) * NB + (J)] = acc[I][0]; \
  stg[cc * STG_STRIDE + (th8 + 2 + tl) * NB + (J)] = acc[I][1]; \
  stg[cc * STG_STRIDE + (th8 + 4 + tl) * NB + (J)] = acc[I][2]; \
  stg[cc * STG_STRIDE + (th8 + 6 + tl) * NB + (J)] = acc[I][3]; }

__global__ void __launch_bounds__(NTH, 1)
main_kernel(const float* __restrict__ x, float* __restrict__ out) {
  extern __shared__ float sm[];
  float* s_w     = sm;
  float* s_x     = sm + SMF_W;
  float* s_binit = sm + SMF_W + SMF_X;
  float* s_rs    = s_binit + SMF_B;
  float* stg     = sm;                 // overlays s_w after compute

  const int tid  = threadIdx.x;
  const int lane = tid & 31;
  const int wid  = tid >> 5;           // warp 0..15
  const int rng  = wid >> 2;           // band range 0..3
  const int sub  = wid & 3;            // SMSP id: (c-half, t-half)
  const int chh  = sub & 1;
  const int th   = sub >> 1;
  const int cl   = lane & 15;
  const int tl   = lane >> 4;
  const int cc   = chh * 16 + cl;      // channel within block 0..31
  const int th8  = th * 8;
  const int c0 = blockIdx.x * CCH;
  const int t0 = blockIdx.y * TT;
  const int b  = blockIdx.z;

  const uint32_t sb = (uint32_t)__cvta_generic_to_shared(sm);

  // ---- cooperative async loads: weights (batch-indep, L2-hot) + x + binit ----
  {
    const float4* gw = (const float4*)(g_fwe + (size_t)c0 * P);
    for (int i = tid; i < CCH * (P / 4); i += NTH)
      cpa16(sb + (uint32_t)i * 16u, gw + i);
    const float2* gx = (const float2*)x + (size_t)(b * TLEN + t0) * ROW2;
    for (int i = tid; i < TT * ROW2; i += NTH) {
      const int r = i / ROW2, pp = i - r * ROW2;
      const int dst = r * (P / 2) + pp + (pp >= 5 ? 1 : 0);
      cpa8(sb + (uint32_t)(SMF_W * 4) + (uint32_t)dst * 8u, gx + i);
    }
    const float4* gb = (const float4*)(g_binit + (size_t)((b << 7) + c0) * NB);
    for (int i = tid; i < (CCH * NB) / 4; i += NTH)
      cpa16(sb + (uint32_t)((SMF_W + SMF_X) * 4) + (uint32_t)i * 16u, gb + i);
    asm volatile("cp.async.commit_group;\n" ::);
  }
  if (tid < NB) s_rs[tid] = g_rstd[b * NB + tid];
  asm volatile("cp.async.wait_group 0;\n" ::);
  if (tid < 2 * TT) s_x[(tid >> 1) * P + 10 + (tid & 1)] = 0.f;  // pad slots
  __syncthreads();

  const float* wr  = s_w + cc * P;
  const float* xr0 = s_x + (th8 + 0 + tl) * P;
  const float* xr1 = s_x + (th8 + 2 + tl) * P;
  const float* xr2 = s_x + (th8 + 4 + tl) * P;
  const float* xr3 = s_x + (th8 + 6 + tl) * P;

  float acc[12][4];

  if      (rng == 0) { RANGE_A(COMPB) }
  else if (rng == 1) { RANGE_B(COMPB) }
  else if (rng == 2) { RANGE_C(COMPB) }
  else               { RANGE_D(COMPB) }

  __syncthreads();     // all smem reads done before stage overlays s_w

  if      (rng == 0) { RANGE_A(STAGEB) }
  else if (rng == 1) { RANGE_B(STAGEB) }
  else if (rng == 2) { RANGE_C(STAGEB) }
  else               { RANGE_D(STAGEB) }
  __syncthreads();

  // coalesced float4 flush: per channel, 16 t-rows contiguous (544 floats)
  const size_t ob0 = ((size_t)((b << 7) + c0) * TLEN + t0) * NB;
#pragma unroll
  for (int k = 0; k < 9; ++k) {
    const int i = tid + (k << 9);
    if (i < 4352) {
      const int c = i / 136;
      const int q = i - c * 136;
      const float4 v = *(const float4*)(stg + c * STG_STRIDE + (q << 2));
      *(float4*)(out + ob0 + (size_t)c * (TLEN * NB) + (q << 2)) = v;
    }
  }
}

// ===== launch =====
extern "C" void kernel_launch(void* const* d_in, const int* in_sizes, int n_in,
                              void* d_out, int out_size) {
  (void)in_sizes; (void)n_in; (void)out_size;
  const float* x = (const float*)d_in[0];
  float* out = (float*)d_out;

  GParams p;
  for (int g = 0; g < 5; ++g) {
    p.nw[g] = (const float*)d_in[1 + 4 * g + 0];
    p.nb[g] = (const float*)d_in[1 + 4 * g + 1];
    p.fw[g] = (const float*)d_in[1 + 4 * g + 2];
    p.fb[g] = (const float*)d_in[1 + 4 * g + 3];
  }

  static bool attr_set = false;
  if (!attr_set) {
    cudaFuncSetAttribute(main_kernel, cudaFuncAttributeMaxDynamicSharedMemorySize, SM_BYTES);
    attr_set = true;
  }

  k1_fused<<<dim3(NB, BATCH, TCH + 1), 128>>>(p, x);
  k2_lite<<<BATCH, 128>>>();
  main_kernel<<<dim3(CTOT / CCH, TLEN / TT, BATCH), NTH, SM_BYTES>>>(x, out);
}

// round 17
// speedup vs baseline: 1.0712x; 1.0033x over previous
#include <cuda_runtime.h>
#include <math.h>
#include <stdint.h>

#define NB    34
#define CTOT  128
#define TLEN  2000
#define BATCH 8
#define ROW2  481
#define P     964
#define CCH   32
#define TT    16
#define NTH   512
#define TCH   8

__constant__ int c_W[NB] = {
  10, 8,8,8,8,8,8,8,8,8,8,8,8,8,8,8,8,8,8,8,
  20,20,20,20,20,20, 80,80,80,80,80,80,80, 120};
__constant__ int c_F0[NB] = {
  0, 10,18,26,34,42,50,58,66,74,82,90,98,106,114,122,130,138,146,154,
  162,182,202,222,242,262, 282,362,442,522,602,682,762, 842};
__constant__ int c_WO[NB] = {
  0, 12,20,28,36,44,52,60,68,76,84,92,100,108,116,124,132,140,148,156,
  164,184,204,224,244,264, 284,364,444,524,604,684,764, 844};
__constant__ int c_G[NB] = {
  0, 1,1,1,1,1,1,1,1,1,1,1,1,1,1,1,1,1,1,1,
  2,2,2,2,2,2, 3,3,3,3,3,3,3, 4};
__constant__ int c_K[NB] = {
  0, 0,1,2,3,4,5,6,7,8,9,10,11,12,13,14,15,16,17,18,
  0,1,2,3,4,5, 0,1,2,3,4,5,6, 0};

__device__ float g_S   [NB * CTOT];
__device__ float g_fbe [NB * CTOT];
__device__ float g_rstd[BATCH * NB];
__device__ float2 g_part[BATCH * NB * TCH];
__device__ __align__(16) float g_fwe  [CTOT * P];           // nw*fw, batch-independent
__device__ __align__(16) float g_binit[BATCH * CTOT * NB];  // fbe - mu*rstd*S

struct GParams {
  const float* nw[5]; const float* nb[5];
  const float* fw[5]; const float* fb[5];
};

// ===== K1: stats (z<TCH) + prep g_fwe/S/fbe (z==TCH, hidden in same launch) =====
__global__ void k1_fused(GParams p, const float* __restrict__ x) {
  const int j = blockIdx.x, b = blockIdx.y, ch = blockIdx.z;
  const int tid = threadIdx.x;       // 128
  if (ch == TCH) {
    if (b != 0) return;              // 34 prep blocks, overlapped with stats
    const int c = tid;
    const int g = c_G[j], k = c_K[j], w = c_W[j], wo = c_WO[j];
    const float* nw = p.nw[g] + k * w;
    const float* nb = p.nb[g] + k * w;
    const float* fw = p.fw[g] + (size_t)(k * CTOT + c) * w;
    float S = 0.f, nbd = 0.f;
    for (int fl = 0; fl < w; ++fl) {
      const float v = nw[fl] * fw[fl];
      g_fwe[c * P + wo + fl] = v;
      S += v;
      nbd = fmaf(nb[fl], fw[fl], nbd);
    }
    if (j == 0) {                    // zero the 2 pad slots of band 0
      g_fwe[c * P + 10] = 0.f;
      g_fwe[c * P + 11] = 0.f;
    }
    g_S  [j * CTOT + c] = S;
    g_fbe[j * CTOT + c] = p.fb[g][k * CTOT + c] + nbd;
    return;
  }
  // ---- partial stats over t-chunk ----
  const int w = c_W[j], f0 = c_F0[j];
  const int t0 = ch * (TLEN / TCH);
  const float2* x2 = (const float2*)x;
  float s = 0.f, q = 0.f;
  const int wh = w >> 1;
  for (int t = tid; t < TLEN / TCH; t += 128) {
    const float2* r = x2 + (size_t)(b * TLEN + t0 + t) * ROW2 + (f0 >> 1);
#pragma unroll 4
    for (int h = 0; h < wh; ++h) {
      float2 v = r[h];
      s += v.x + v.y;
      q = fmaf(v.x, v.x, q);
      q = fmaf(v.y, v.y, q);
    }
  }
#pragma unroll
  for (int o = 16; o; o >>= 1) {
    s += __shfl_down_sync(0xffffffffu, s, o);
    q += __shfl_down_sync(0xffffffffu, q, o);
  }
  __shared__ float ss[4], qs[4];
  const int lane = tid & 31, wid = tid >> 5;
  if (lane == 0) { ss[wid] = s; qs[wid] = q; }
  __syncthreads();
  if (tid == 0) {
    g_part[(b * NB + j) * TCH + ch] =
      make_float2(ss[0]+ss[1]+ss[2]+ss[3], qs[0]+qs[1]+qs[2]+qs[3]);
  }
}

// ===== K2-lite: reduce stats -> rstd + binit (tiny) =====
__global__ void k2_lite(void) {
  const int b = blockIdx.x;          // 0..7
  const int c = threadIdx.x;         // 128
  __shared__ float s_mu[NB], s_rs[NB];
  if (c < NB) {
    const int j = c;
    float S = 0.f, Q = 0.f;
#pragma unroll
    for (int k = 0; k < TCH; ++k) {
      float2 v = g_part[(b * NB + j) * TCH + k];
      S += v.x; Q += v.y;
    }
    const float invN = 1.f / (float)(TLEN * c_W[j]);
    const float mu = S * invN;
    const float rs = rsqrtf(Q * invN - mu * mu + 1e-5f);
    s_mu[j] = mu; s_rs[j] = rs;
    g_rstd[b * NB + j] = rs;
  }
  __syncthreads();
#pragma unroll 2
  for (int j = 0; j < NB; ++j) {
    g_binit[(size_t)(b * CTOT + c) * NB + j] =
      g_fbe[j * CTOT + c] - s_mu[j] * s_rs[j] * g_S[j * CTOT + c];
  }
}

// ===== main: R15-measured compute (278.9 us), batch-indep weights + rstd fold =====
#define SMF_W  (CCH * P)
#define SMF_X  (TT * P)
#define SMF_B  (CCH * NB)
#define SM_BYTES  ((SMF_W + SMF_X + SMF_B + 40) * 4)
#define STG_STRIDE 548     // 2192 B, 16B-aligned

// X(accIdx, band, paddedOffset, width). Range widths 236/252/240/236.
#define RANGE_A(X) \
  X(0,33,844,120) X(1,0,0,12) X(2,1,12,8) X(3,2,20,8) X(4,3,28,8) X(5,4,36,8) \
  X(6,5,44,8) X(7,6,52,8) X(8,7,60,8) X(9,8,68,8) X(10,23,224,20) X(11,24,244,20)
#define RANGE_B(X) \
  X(0,32,764,80) X(1,26,284,80) X(2,9,76,8) X(3,10,84,8) X(4,11,92,8) X(5,12,100,8) \
  X(6,13,108,8) X(7,14,116,8) X(8,15,124,8) X(9,16,132,8) X(10,17,140,8) X(11,25,264,20)
#define RANGE_C(X) X(0,27,364,80) X(1,28,444,80) X(2,29,524,80)
#define RANGE_D(X) \
  X(0,30,604,80) X(1,31,684,80) X(2,18,148,8) X(3,19,156,8) X(4,20,164,20) \
  X(5,21,184,20) X(6,22,204,20)

__device__ __forceinline__ void cpa16(uint32_t s, const void* g) {
  asm volatile("cp.async.cg.shared.global [%0], [%1], 16;\n" :: "r"(s), "l"(g));
}
__device__ __forceinline__ void cpa8(uint32_t s, const void* g) {
  asm volatile("cp.async.ca.shared.global [%0], [%1], 8;\n" :: "r"(s), "l"(g));
}
__device__ __forceinline__ void fma2(unsigned long long& a,
                                     unsigned long long xv,
                                     unsigned long long wv) {
  asm("fma.rn.f32x2 %0, %1, %2, %0;" : "+l"(a) : "l"(xv), "l"(wv));
}
__device__ __forceinline__ float hadd2(unsigned long long a) {
  float lo, hi;
  asm("mov.b64 {%0, %1}, %2;" : "=f"(lo), "=f"(hi) : "l"(a));
  return lo + hi;
}

// per band: f32x2 partials over even/odd f; fold bias + rstd scale at end
#define COMPB(I, J, WO, WL) { \
  unsigned long long a0 = 0ull, a1 = 0ull, a2 = 0ull, a3 = 0ull; \
  _Pragma("unroll") \
  for (int f = 0; f < (WL); f += 4) { \
    const ulonglong2 wv = *(const ulonglong2*)(wr  + (WO) + f); \
    const ulonglong2 v0 = *(const ulonglong2*)(xr0 + (WO) + f); \
    const ulonglong2 v1 = *(const ulonglong2*)(xr1 + (WO) + f); \
    const ulonglong2 v2 = *(const ulonglong2*)(xr2 + (WO) + f); \
    const ulonglong2 v3 = *(const ulonglong2*)(xr3 + (WO) + f); \
    fma2(a0, v0.x, wv.x); fma2(a0, v0.y, wv.y); \
    fma2(a1, v1.x, wv.x); fma2(a1, v1.y, wv.y); \
    fma2(a2, v2.x, wv.x); fma2(a2, v2.y, wv.y); \
    fma2(a3, v3.x, wv.x); fma2(a3, v3.y, wv.y); \
  } \
  { const float bi = s_binit[cc * NB + (J)]; \
    const float rs = s_rs[(J)]; \
    acc[I][0] = fmaf(rs, hadd2(a0), bi); \
    acc[I][1] = fmaf(rs, hadd2(a1), bi); \
    acc[I][2] = fmaf(rs, hadd2(a2), bi); \
    acc[I][3] = fmaf(rs, hadd2(a3), bi); } }

// thread's t rows: t(q) = th8 + 2q + tl
#define STAGEB(I, J, WO, WL) { \
  stg[cc * STG_STRIDE + (th8 + 0 + tl) * NB + (J)] = acc[I][0]; \
  stg[cc * STG_STRIDE + (th8 + 2 + tl) * NB + (J)] = acc[I][1]; \
  stg[cc * STG_STRIDE + (th8 + 4 + tl) * NB + (J)] = acc[I][2]; \
  stg[cc * STG_STRIDE + (th8 + 6 + tl) * NB + (J)] = acc[I][3]; }

__global__ void __launch_bounds__(NTH, 1)
main_kernel(const float* __restrict__ x, float* __restrict__ out) {
  extern __shared__ float sm[];
  float* s_w     = sm;
  float* s_x     = sm + SMF_W;
  float* s_binit = sm + SMF_W + SMF_X;
  float* s_rs    = s_binit + SMF_B;
  float* stg     = sm;                 // overlays s_w after compute

  const int tid  = threadIdx.x;
  const int lane = tid & 31;
  const int wid  = tid >> 5;           // warp 0..15
  const int rng  = wid >> 2;           // band range 0..3
  const int sub  = wid & 3;            // SMSP id: (c-half, t-half)
  const int chh  = sub & 1;
  const int th   = sub >> 1;
  const int cl   = lane & 15;
  const int tl   = lane >> 4;
  const int cc   = chh * 16 + cl;      // channel within block 0..31
  const int th8  = th * 8;
  const int c0 = blockIdx.x * CCH;
  const int t0 = blockIdx.y * TT;
  const int b  = blockIdx.z;

  const uint32_t sb = (uint32_t)__cvta_generic_to_shared(sm);

  // ---- cooperative async loads: weights (batch-indep, L2-hot) + x + binit ----
  {
    const float4* gw = (const float4*)(g_fwe + (size_t)c0 * P);
    for (int i = tid; i < CCH * (P / 4); i += NTH)
      cpa16(sb + (uint32_t)i * 16u, gw + i);
    const float2* gx = (const float2*)x + (size_t)(b * TLEN + t0) * ROW2;
    for (int i = tid; i < TT * ROW2; i += NTH) {
      const int r = i / ROW2, pp = i - r * ROW2;
      const int dst = r * (P / 2) + pp + (pp >= 5 ? 1 : 0);
      cpa8(sb + (uint32_t)(SMF_W * 4) + (uint32_t)dst * 8u, gx + i);
    }
    const float4* gb = (const float4*)(g_binit + (size_t)((b << 7) + c0) * NB);
    for (int i = tid; i < (CCH * NB) / 4; i += NTH)
      cpa16(sb + (uint32_t)((SMF_W + SMF_X) * 4) + (uint32_t)i * 16u, gb + i);
    asm volatile("cp.async.commit_group;\n" ::);
  }
  if (tid < NB) s_rs[tid] = g_rstd[b * NB + tid];
  asm volatile("cp.async.wait_group 0;\n" ::);
  if (tid < 2 * TT) s_x[(tid >> 1) * P + 10 + (tid & 1)] = 0.f;  // pad slots
  __syncthreads();

  const float* wr  = s_w + cc * P;
  const float* xr0 = s_x + (th8 + 0 + tl) * P;
  const float* xr1 = s_x + (th8 + 2 + tl) * P;
  const float* xr2 = s_x + (th8 + 4 + tl) * P;
  const float* xr3 = s_x + (th8 + 6 + tl) * P;

  float acc[12][4];

  if      (rng == 0) { RANGE_A(COMPB) }
  else if (rng == 1) { RANGE_B(COMPB) }
  else if (rng == 2) { RANGE_C(COMPB) }
  else               { RANGE_D(COMPB) }

  __syncthreads();     // all smem reads done before stage overlays s_w

  if      (rng == 0) { RANGE_A(STAGEB) }
  else if (rng == 1) { RANGE_B(STAGEB) }
  else if (rng == 2) { RANGE_C(STAGEB) }
  else               { RANGE_D(STAGEB) }
  __syncthreads();

  // coalesced float4 flush: per channel, 16 t-rows contiguous (544 floats)
  const size_t ob0 = ((size_t)((b << 7) + c0) * TLEN + t0) * NB;
#pragma unroll
  for (int k = 0; k < 9; ++k) {
    const int i = tid + (k << 9);
    if (i < 4352) {
      const int c = i / 136;
      const int q = i - c * 136;
      const float4 v = *(const float4*)(stg + c * STG_STRIDE + (q << 2));
      *(float4*)(out + ob0 + (size_t)c * (TLEN * NB) + (q << 2)) = v;
    }
  }
}

// ===== launch =====
extern "C" void kernel_launch(void* const* d_in, const int* in_sizes, int n_in,
                              void* d_out, int out_size) {
  (void)in_sizes; (void)n_in; (void)out_size;
  const float* x = (const float*)d_in[0];
  float* out = (float*)d_out;

  GParams p;
  for (int g = 0; g < 5; ++g) {
    p.nw[g] = (const float*)d_in[1 + 4 * g + 0];
    p.nb[g] = (const float*)d_in[1 + 4 * g + 1];
    p.fw[g] = (const float*)d_in[1 + 4 * g + 2];
    p.fb[g] = (const float*)d_in[1 + 4 * g + 3];
  }

  static bool attr_set = false;
  if (!attr_set) {
    cudaFuncSetAttribute(main_kernel, cudaFuncAttributeMaxDynamicSharedMemorySize, SM_BYTES);
    attr_set = true;
  }

  k1_fused<<<dim3(NB, BATCH, TCH + 1), 128>>>(p, x);
  k2_lite<<<BATCH, 128>>>();
  main_kernel<<<dim3(CTOT / CCH, TLEN / TT, BATCH), NTH, SM_BYTES>>>(x, out);
}